// round 16
// baseline (speedup 1.0000x reference)
#include <cuda_runtime.h>
#include <cuda_bf16.h>
#include <math.h>

// Problem constants
#define VOCAB 50000
#define D_EMB 256
#define H_DIM 512
#define B_SZ  64
#define T_LEN 512
#define KTOT  (D_EMB + H_DIM)   // 768
#define G4H   (4 * H_DIM)       // 2048

// k-pair decomposition: f32x2 lanes = (even k, odd k)
#define KP_TOT (KTOT / 2)       // 384 k-pairs
#define XKP    (D_EMB / 2)      // 128 x k-pairs
#define HKP    (H_DIM / 2)      // 256 h k-pairs

// Persistent-kernel config
#define NCTA  128               // CTA owns 4 h-cols -> 16 gate cols
#define NTHR  1024              // 32 warps = 16 k-groups x 2 batch-halves
#define NKG   16
#define HC    4
#define XKP_W (XKP / NKG)       // 8  x k-pairs per k-group
#define HKP_W (HKP / NKG)       // 16 h k-pairs per k-group

// act row = 128 floats: [b][parity] interleaved
#define AROW 128
// weight row per kpair per CTA = 16 float2 = 128B (one cache line)
#define WROW 16

#define RED_F      (32 * 16 * 32)    // red[w][e][lane] = 16384 floats
#define SMEM_BYTES (RED_F * 4)       // 64KB -> dynamic smem

typedef unsigned long long u64;

// -------- device scratch --------
__device__ float    g_XT[T_LEN * XKP * AROW];     // [t][kp][b*2+par]
__device__ float    g_hp[2][HKP * AROW];          // [kp][b*2+par] double buffer
__device__ float2   g_Wp[KP_TOT][NCTA][WROW];     // {w_2kp, w_2kp+1} per col
__device__ unsigned g_bar_count;
__device__ unsigned g_bar_gen;

__device__ __forceinline__ u64 fma2(u64 a, u64 b, u64 c) {
    u64 d; asm("fma.rn.f32x2 %0, %1, %2, %3;" : "=l"(d) : "l"(a), "l"(b), "l"(c)); return d;
}
__device__ __forceinline__ float sigf(float x) { return 1.0f / (1.0f + __expf(-x)); }

// ============================================================================
// Kernel 1a: embedding gather -> k-pair-interleaved transpose; zero h0; bar reset.
// ============================================================================
__global__ void gather_transpose_kernel(const int* __restrict__ wi,
                                        const float* __restrict__ emb) {
    int t   = blockIdx.x;
    int tid = threadIdx.x;
    int b   = tid & 63;
    int q   = tid >> 6;

    int row = wi[b * T_LEN + t];
    const float* er = emb + (size_t)row * D_EMB + q * 64;
    float* xo = g_XT + (size_t)t * (XKP * AROW);

#pragma unroll
    for (int i = 0; i < 64; i += 4) {
        float4 v = __ldg((const float4*)(er + i));
        int d = q * 64 + i;      // even k
        *(float2*)&xo[(d >> 1) * AROW + b * 2]       = make_float2(v.x, v.y);
        *(float2*)&xo[((d >> 1) + 1) * AROW + b * 2] = make_float2(v.z, v.w);
    }
    // zero h buffer 0 (32768 floats)
    if (t < 128) g_hp[0][t * 256 + tid] = 0.0f;
    if (t == 0 && tid == 0) { g_bar_gen = 0; g_bar_count = 0; }
}

// ============================================================================
// Kernel 1b: pack weights as k-pairs, per-CTA contiguous 128B lines.
// ============================================================================
__global__ void pack_weights_kernel(const float* __restrict__ kern) {
    int kp  = blockIdx.x;        // 0..383
    int tid = threadIdx.x;       // 256
    const float* r0 = kern + (size_t)(2 * kp) * G4H;
    const float* r1 = r0 + G4H;
    for (int e = tid; e < NCTA * WROW; e += 256) {
        int cta = e >> 4, c = e & 15;
        int col = (c >> 2) * H_DIM + cta * 4 + (c & 3);
        g_Wp[kp][cta][c] = make_float2(r0[col], r1[col]);
    }
}

// ============================================================================
// Kernel 2: persistent LSTM, 128 CTAs x 1024 threads (32 warps).
//  - warp w = (kg = w>>1, bh = w&1): k-pair 16th, batch-half
//  - lane (bg = lane>>2, cg = lane&3): 4 batches (i) x 4 cols (j), acc[4][4]
//  - f32x2 lanes = (k even, k odd): zero-broadcast outer product
//  - 8 warps/SMSP to hide L2 act latency; weights L1-resident
//  - x-GEMM for step t+1 overlapped with the grid barrier wait
// ============================================================================

// per k-pair: 4x LDG.128 + 16 FFMA2 (covers 2 k's)
#define KPBODY(AP, WP)                                              \
    {                                                               \
        const ulonglong2* _a = (const ulonglong2*)(AP);             \
        const ulonglong2* _w = (const ulonglong2*)(WP);             \
        ulonglong2 va0 = __ldcg(_a);                                \
        ulonglong2 va1 = __ldcg(_a + 1);                            \
        ulonglong2 wv0 = _w[0];                                     \
        ulonglong2 wv1 = _w[1];                                     \
        acc[0][0] = fma2(va0.x, wv0.x, acc[0][0]);                  \
        acc[0][1] = fma2(va0.x, wv0.y, acc[0][1]);                  \
        acc[0][2] = fma2(va0.x, wv1.x, acc[0][2]);                  \
        acc[0][3] = fma2(va0.x, wv1.y, acc[0][3]);                  \
        acc[1][0] = fma2(va0.y, wv0.x, acc[1][0]);                  \
        acc[1][1] = fma2(va0.y, wv0.y, acc[1][1]);                  \
        acc[1][2] = fma2(va0.y, wv1.x, acc[1][2]);                  \
        acc[1][3] = fma2(va0.y, wv1.y, acc[1][3]);                  \
        acc[2][0] = fma2(va1.x, wv0.x, acc[2][0]);                  \
        acc[2][1] = fma2(va1.x, wv0.y, acc[2][1]);                  \
        acc[2][2] = fma2(va1.x, wv1.x, acc[2][2]);                  \
        acc[2][3] = fma2(va1.x, wv1.y, acc[2][3]);                  \
        acc[3][0] = fma2(va1.y, wv0.x, acc[3][0]);                  \
        acc[3][1] = fma2(va1.y, wv0.y, acc[3][1]);                  \
        acc[3][2] = fma2(va1.y, wv1.x, acc[3][2]);                  \
        acc[3][3] = fma2(va1.y, wv1.y, acc[3][3]);                  \
    }

#define WKP_STRIDE (NCTA * WROW)    // float2 per k-pair row

__global__ void __launch_bounds__(NTHR, 1)
lstm_persistent_kernel(const float* __restrict__ bias,
                       const int*   __restrict__ num_words,
                       float*       __restrict__ out) {
    extern __shared__ float red[];    // [w][e=i*4+j][lane], 32*16*32

    const int tid  = threadIdx.x;
    const int w    = tid >> 5;
    const int lane = tid & 31;
    const int kg   = w >> 1;
    const int bh   = w & 1;
    const int bg   = lane >> 2;
    const int cg   = lane & 3;
    const int hc0  = blockIdx.x * HC;

    // ---- epilogue-role state (tid < 256) ----
    const int b  = tid & 63;
    const int cl = (tid >> 6) & 3;
    float c_reg = 0.0f, h_reg = 0.0f;
    int nw_b = 0;
    float biasr[4] = {0.f, 0.f, 0.f, 0.f};
    if (tid < 256) {
        nw_b = num_words[b];
#pragma unroll
        for (int g = 0; g < 4; ++g) biasr[g] = bias[g * H_DIM + hc0 + cl];
    }

    const int actoff = bh * 64 + bg * 8;                       // floats into AROW
    const float2* wx0 = &g_Wp[kg * XKP_W][blockIdx.x][cg * 4];
    const float2* wh0 = &g_Wp[XKP + kg * HKP_W][blockIdx.x][cg * 4];

    u64 acc[4][4];

    // ---- prologue: x-part for t = 0 ----
    {
#pragma unroll
        for (int i = 0; i < 4; ++i)
#pragma unroll
            for (int j = 0; j < 4; ++j) acc[i][j] = 0ull;
        const float*  ap = g_XT + (kg * XKP_W) * AROW + actoff;
        const float2* wp = wx0;
#pragma unroll 4
        for (int kk = 0; kk < XKP_W; ++kk) {
            KPBODY(ap, wp);
            ap += AROW; wp += WKP_STRIDE;
        }
    }

    for (int t = 0; t < T_LEN; ++t) {
        if (t > 0) {
            // ---- wait for h(t), then accumulate h-part ----
            if (tid == 0) {
                while (*(volatile unsigned*)&g_bar_gen < (unsigned)t) { __nanosleep(32); }
                __threadfence();
            }
            __syncthreads();
            const float*  ap = g_hp[t & 1] + (kg * HKP_W) * AROW + actoff;
            const float2* wp = wh0;
#pragma unroll 4
            for (int kk = 0; kk < HKP_W; ++kk) {
                KPBODY(ap, wp);
                ap += AROW; wp += WKP_STRIDE;
            }
        }

        // ---- fold k-parity (FADD) + dump: red[w][i*4+j][lane], conflict-free ----
        {
            float* base = red + w * (16 * 32) + lane;
#pragma unroll
            for (int i = 0; i < 4; ++i)
#pragma unroll
                for (int j = 0; j < 4; ++j) {
                    float2 f = *(float2*)&acc[i][j];
                    base[(i * 4 + j) * 32] = f.x + f.y;
                }
        }
        __syncthreads();

        // ---- reduce over 16 k-groups + activations + state update ----
        if (tid < 256) {
            const int bhh = b >> 5;
            const int bgg = (b >> 2) & 7;
            const int ii  = b & 3;
            // value (b, col=cl, gate g) at red[kg*2+bhh][ii*4+cl][bgg*4+g]
            const float* rp = red + bhh * (16 * 32) + (ii * 4 + cl) * 32 + bgg * 4;
            float g4[4] = {biasr[0], biasr[1], biasr[2], biasr[3]};
#pragma unroll
            for (int kgi = 0; kgi < NKG; ++kgi) {
                float4 v = *(const float4*)(rp + kgi * (2 * 16 * 32));
                g4[0] += v.x; g4[1] += v.y; g4[2] += v.z; g4[3] += v.w;
            }
            float ig = sigf(g4[0]);
            float jt = tanhf(g4[1]);
            float fg = sigf(g4[2] + 1.0f);
            float og = sigf(g4[3]);
            float cn = fg * c_reg + ig * jt;
            float hn = og * tanhf(cn);
            if (t < nw_b) { c_reg = cn; h_reg = hn; }
            // paired h store: g_hp[buf][ (hcol>>1)*AROW + b*2 + (hcol&1) ]
            int hcol = hc0 + cl;
            g_hp[(t + 1) & 1][(hcol >> 1) * AROW + b * 2 + (hcol & 1)] = h_reg;
        }
        __syncthreads();   // h CTA-visible; red reads done before next dump

        // ---- arrive (non-blocking), then overlap x-part of t+1 ----
        if (tid == 0) {
            __threadfence();
            unsigned tkt = atomicAdd(&g_bar_count, 1u);
            if (tkt == NCTA - 1) {
                atomicExch(&g_bar_count, 0u);
                __threadfence();
                atomicAdd(&g_bar_gen, 1u);   // gen = t+1
            }
        }
        if (t + 1 < T_LEN) {
#pragma unroll
            for (int i = 0; i < 4; ++i)
#pragma unroll
                for (int j = 0; j < 4; ++j) acc[i][j] = 0ull;
            const float*  ap = g_XT + (size_t)(t + 1) * (XKP * AROW)
                               + (kg * XKP_W) * AROW + actoff;
            const float2* wp = wx0;
#pragma unroll 4
            for (int kk = 0; kk < XKP_W; ++kk) {
                KPBODY(ap, wp);
                ap += AROW; wp += WKP_STRIDE;
            }
        }
    }

    // ---- final output [2, B, H] ----
    if (tid < 256) {
        out[(size_t)b * H_DIM + hc0 + cl]                = c_reg;
        out[(size_t)B_SZ * H_DIM + b * H_DIM + hc0 + cl] = h_reg;
    }
}

// ============================================================================
extern "C" void kernel_launch(void* const* d_in, const int* in_sizes, int n_in,
                              void* d_out, int out_size) {
    const int*   wi   = (const int*)d_in[0];
    const int*   nw   = (const int*)d_in[1];
    const float* emb  = (const float*)d_in[2];
    const float* kern = (const float*)d_in[3];
    const float* bias = (const float*)d_in[4];
    float* out = (float*)d_out;

    cudaFuncSetAttribute(lstm_persistent_kernel,
                         cudaFuncAttributeMaxDynamicSharedMemorySize, SMEM_BYTES);
    // smem 64KB; keep the rest of L1D for the 48KB/CTA weight slice
    cudaFuncSetAttribute(lstm_persistent_kernel,
                         cudaFuncAttributePreferredSharedMemoryCarveout, 29);

    gather_transpose_kernel<<<T_LEN, 256>>>(wi, emb);
    pack_weights_kernel<<<KP_TOT, 256>>>(kern);
    lstm_persistent_kernel<<<NCTA, NTHR, SMEM_BYTES>>>(bias, nw, out);
}